// round 5
// baseline (speedup 1.0000x reference)
#include <cuda_runtime.h>
#include <cuda_bf16.h>
#include <cstdint>

#define NNODES 100000
#define NEDGES 1600000

// ---------------- scratch (static __device__ — allocation-free) ----------------
__device__ int g_deg[NNODES], g_rowptr[NNODES], g_cursor[NNODES], g_col[NEDGES];
__device__ int g_bsum[512], g_boff[512];
// bf16 hi/lo plane storage for all features
__device__ __nv_bfloat16 g_xh[NNODES * 64],   g_xl[NNODES * 64];
__device__ __nv_bfloat16 g_mh[NNODES * 128],  g_ml[NNODES * 128];
__device__ __nv_bfloat16 g_h1h[NNODES * 128], g_h1l[NNODES * 128];
__device__ __nv_bfloat16 g_h2h[NNODES * 128], g_h2l[NNODES * 128];
__device__ __nv_bfloat16 g_h3h[NNODES * 256], g_h3l[NNODES * 256];
__device__ __nv_bfloat16 g_wth[256 * 256],    g_wtl[256 * 256];

// ---------------- helpers ----------------
__device__ __forceinline__ uint32_t sw64(uint32_t b) { return b ^ ((b >> 3) & 0x30); }
__device__ __forceinline__ uint32_t cvta_smem(const void* p) {
    uint32_t a;
    asm("{ .reg .u64 t; cvta.to.shared.u64 t, %1; cvt.u32.u64 %0, t; }" : "=r"(a) : "l"(p));
    return a;
}
__device__ __forceinline__ void cpa16(uint32_t dst, const void* src, int sz) {
    asm volatile("cp.async.cg.shared.global [%0], [%1], 16, %2;"
                 :: "r"(dst), "l"(src), "r"(sz) : "memory");
}
__device__ __forceinline__ void ldsm4(uint32_t& r0, uint32_t& r1, uint32_t& r2, uint32_t& r3,
                                      uint32_t addr) {
    asm volatile("ldmatrix.sync.aligned.m8n8.x4.shared.b16 {%0,%1,%2,%3}, [%4];"
                 : "=r"(r0), "=r"(r1), "=r"(r2), "=r"(r3) : "r"(addr));
}
__device__ __forceinline__ void mma16816(float* c, const uint32_t* a, uint32_t b0, uint32_t b1) {
    asm volatile(
        "mma.sync.aligned.m16n8k16.row.col.f32.bf16.bf16.f32 "
        "{%0,%1,%2,%3}, {%4,%5,%6,%7}, {%8,%9}, {%0,%1,%2,%3};"
        : "+f"(c[0]), "+f"(c[1]), "+f"(c[2]), "+f"(c[3])
        : "r"(a[0]), "r"(a[1]), "r"(a[2]), "r"(a[3]), "r"(b0), "r"(b1));
}
__device__ __forceinline__ void split2(float v, __nv_bfloat16& h, __nv_bfloat16& l) {
    h = __float2bfloat16(v);
    l = __float2bfloat16(v - __bfloat162float(h));
}
// split 4 fp32 -> 8B hi plane + 8B lo plane
__device__ __forceinline__ void split4(float4 v, uint2& H, uint2& L) {
    __nv_bfloat16 h0, l0, h1, l1, h2, l2, h3, l3;
    split2(v.x, h0, l0); split2(v.y, h1, l1);
    split2(v.z, h2, l2); split2(v.w, h3, l3);
    __nv_bfloat162 ph0 = __halves2bfloat162(h0, h1), ph1 = __halves2bfloat162(h2, h3);
    __nv_bfloat162 pl0 = __halves2bfloat162(l0, l1), pl1 = __halves2bfloat162(l2, l3);
    H = make_uint2(*(uint32_t*)&ph0, *(uint32_t*)&ph1);
    L = make_uint2(*(uint32_t*)&pl0, *(uint32_t*)&pl1);
}
// accumulate 4 reconstructed floats from hi/lo plane words
__device__ __forceinline__ void acc4(uint2 H, uint2 L,
                                     float& a0, float& a1, float& a2, float& a3) {
    float2 h0 = __bfloat1622float2(*(__nv_bfloat162*)&H.x);
    float2 h1 = __bfloat1622float2(*(__nv_bfloat162*)&H.y);
    float2 l0 = __bfloat1622float2(*(__nv_bfloat162*)&L.x);
    float2 l1 = __bfloat1622float2(*(__nv_bfloat162*)&L.y);
    a0 += h0.x + l0.x; a1 += h0.y + l0.y;
    a2 += h1.x + l1.x; a3 += h1.y + l1.y;
}

// ---------------- CSR build ----------------
__global__ void k_zero_deg(int n) {
    int i = blockIdx.x * blockDim.x + threadIdx.x;
    if (i < n) g_deg[i] = 0;
}
__global__ void k_count(const int* __restrict__ dst, int E) {
    int e = blockIdx.x * blockDim.x + threadIdx.x;
    if (e < E) atomicAdd(&g_deg[dst[e]], 1);
}
__global__ void k_scan1(int n) {
    int tid = threadIdx.x, lane = tid & 31, warp = tid >> 5;
    int i = blockIdx.x * 256 + tid;
    int v = (i < n) ? g_deg[i] : 0;
    int x = v;
    #pragma unroll
    for (int o = 1; o < 32; o <<= 1) {
        int t = __shfl_up_sync(0xffffffffu, x, o);
        if (lane >= o) x += t;
    }
    __shared__ int wq[8];
    if (lane == 31) wq[warp] = x;
    __syncthreads();
    if (warp == 0) {
        int y = (lane < 8) ? wq[lane] : 0;
        int z = y;
        #pragma unroll
        for (int o = 1; o < 8; o <<= 1) {
            int t = __shfl_up_sync(0xffffffffu, z, o);
            if (lane >= o) z += t;
        }
        if (lane < 8) wq[lane] = z - y;
        if (lane == 7) g_bsum[blockIdx.x] = z;
    }
    __syncthreads();
    if (i < n) g_rowptr[i] = wq[warp] + x - v;
}
__global__ void k_scan2(int nb) {
    int tid = threadIdx.x, lane = tid & 31, warp = tid >> 5;
    int v = (tid < nb) ? g_bsum[tid] : 0;
    int x = v;
    #pragma unroll
    for (int o = 1; o < 32; o <<= 1) {
        int t = __shfl_up_sync(0xffffffffu, x, o);
        if (lane >= o) x += t;
    }
    __shared__ int wq[16];
    if (lane == 31) wq[warp] = x;
    __syncthreads();
    if (warp == 0) {
        int y = (lane < 16) ? wq[lane] : 0;
        int z = y;
        #pragma unroll
        for (int o = 1; o < 16; o <<= 1) {
            int t = __shfl_up_sync(0xffffffffu, z, o);
            if (lane >= o) z += t;
        }
        if (lane < 16) wq[lane] = z - y;
    }
    __syncthreads();
    if (tid < nb) g_boff[tid] = wq[warp] + x - v;
}
__global__ void k_scan3(int n) {
    int i = blockIdx.x * blockDim.x + threadIdx.x;
    if (i < n) {
        int r = g_rowptr[i] + g_boff[i >> 8];
        g_rowptr[i] = r;
        g_cursor[i] = r;
    }
}
__global__ void k_fill(const int* __restrict__ src, const int* __restrict__ dst, int E) {
    int e = blockIdx.x * blockDim.x + threadIdx.x;
    if (e < E) {
        int p = atomicAdd(&g_cursor[dst[e]], 1);
        g_col[p] = src[e];
    }
}

// ---------------- input / weight prep ----------------
__global__ void k_split_x(const float* __restrict__ x, int n4) {
    int i = blockIdx.x * blockDim.x + threadIdx.x;
    if (i < n4) {
        float4 v = *(const float4*)(x + i * 4);
        uint2 H, L; split4(v, H, L);
        *(uint2*)(g_xh + i * 4) = H;
        *(uint2*)(g_xl + i * 4) = L;
    }
}
// Wt[n][k] = (k<K1 ? Wl[k][n] : Wr[k-K1][n]) split into planes
__global__ void k_prep_w(const float* __restrict__ Wl, const float* __restrict__ Wr,
                         int K1, int KT, int N) {
    int i = blockIdx.x * blockDim.x + threadIdx.x;
    if (i >= N * KT) return;
    int n = i / KT, k = i % KT;
    float v = (k < K1) ? Wl[k * N + n] : Wr[(k - K1) * N + n];
    __nv_bfloat16 h, l; split2(v, h, l);
    g_wth[n * KT + k] = h;
    g_wtl[n * KT + k] = l;
}

// ---------------- aggregation: layer 1 (fp32 x, D=64) -> m planes[M,64] ----------------
__global__ void k_agg1(const float* __restrict__ x, int n) {
    int gt = blockIdx.x * blockDim.x + threadIdx.x;
    int node = gt >> 5, lane = gt & 31;
    if (node >= n) return;
    float a0 = 0.f, a1 = 0.f;
    int s = g_rowptr[node], d = g_deg[node];
    int e = s, end = s + d;
    for (; e + 1 < end; e += 2) {
        float2 p0 = *(const float2*)(x + (size_t)g_col[e]     * 64 + 2 * lane);
        float2 p1 = *(const float2*)(x + (size_t)g_col[e + 1] * 64 + 2 * lane);
        a0 += p0.x + p1.x; a1 += p0.y + p1.y;
    }
    if (e < end) {
        float2 p0 = *(const float2*)(x + (size_t)g_col[e] * 64 + 2 * lane);
        a0 += p0.x; a1 += p0.y;
    }
    float inv = 1.0f / (float)(d > 0 ? d : 1);
    a0 *= inv; a1 *= inv;
    __nv_bfloat16 h0, l0, h1, l1;
    split2(a0, h0, l0); split2(a1, h1, l1);
    __nv_bfloat162 ph = __halves2bfloat162(h0, h1), pl = __halves2bfloat162(l0, l1);
    size_t o = (size_t)node * 64 + 2 * lane;
    *(uint32_t*)(g_mh + o) = *(uint32_t*)&ph;
    *(uint32_t*)(g_ml + o) = *(uint32_t*)&pl;
}

// ---------------- aggregation: layers 2/3 (hi/lo planes, D=128) -> m planes[M,128] ----------------
__global__ void k_agg2(const __nv_bfloat16* __restrict__ hh,
                       const __nv_bfloat16* __restrict__ hl, int n) {
    int gt = blockIdx.x * blockDim.x + threadIdx.x;
    int node = gt >> 5, lane = gt & 31;
    if (node >= n) return;
    float a0 = 0.f, a1 = 0.f, a2 = 0.f, a3 = 0.f;
    int s = g_rowptr[node], d = g_deg[node];
    int e = s, end = s + d;
    for (; e + 1 < end; e += 2) {
        size_t b0 = (size_t)g_col[e]     * 128 + 4 * lane;
        size_t b1 = (size_t)g_col[e + 1] * 128 + 4 * lane;
        uint2 H0 = *(const uint2*)(hh + b0), L0 = *(const uint2*)(hl + b0);
        uint2 H1 = *(const uint2*)(hh + b1), L1 = *(const uint2*)(hl + b1);
        acc4(H0, L0, a0, a1, a2, a3);
        acc4(H1, L1, a0, a1, a2, a3);
    }
    if (e < end) {
        size_t b0 = (size_t)g_col[e] * 128 + 4 * lane;
        uint2 H0 = *(const uint2*)(hh + b0), L0 = *(const uint2*)(hl + b0);
        acc4(H0, L0, a0, a1, a2, a3);
    }
    float inv = 1.0f / (float)(d > 0 ? d : 1);
    uint2 H, L;
    split4(make_float4(a0 * inv, a1 * inv, a2 * inv, a3 * inv), H, L);
    size_t o = (size_t)node * 128 + 4 * lane;
    *(uint2*)(g_mh + o) = H;
    *(uint2*)(g_ml + o) = L;
}

// ---------------- cp.async double-buffered HMMA GEMM ----------------
// out planes = relu([A1|A2] @ Wt^T + bias), split back to hi/lo bf16
// CTA 128x128, BK=32, 2 stages. Stage layout: AH 0, AL 8K, WH 16K, WL 24K (32KB/stage)
#define SM_TOT 65536

template <int K1, int K2, int NT>
__global__ void __launch_bounds__(256, 2) k_gemm_cp(
    const __nv_bfloat16* __restrict__ A1h, const __nv_bfloat16* __restrict__ A1l,
    const __nv_bfloat16* __restrict__ A2h, const __nv_bfloat16* __restrict__ A2l,
    const __nv_bfloat16* __restrict__ Wph, const __nv_bfloat16* __restrict__ Wpl,
    const float* __restrict__ bias,
    __nv_bfloat16* __restrict__ Oh, __nv_bfloat16* __restrict__ Ol, int M)
{
    extern __shared__ char smem[];
    constexpr int KT = K1 + K2;
    constexpr int NC = KT / 32;
    uint32_t sb = cvta_smem(smem);
    int tid = threadIdx.x, lane = tid & 31, wid = tid >> 5;
    int wm = wid & 1, wn = wid >> 1;                       // 2m x 4n warp grid
    int bm = blockIdx.y * 128, bn = blockIdx.x * 128;

    float acc[4][4][4];
    #pragma unroll
    for (int mt = 0; mt < 4; mt++)
        #pragma unroll
        for (int nt = 0; nt < 4; nt++)
            #pragma unroll
            for (int j = 0; j < 4; j++) acc[mt][nt][j] = 0.f;

    // per-lane ldmatrix address components (x4, non-trans) — same mapping as R4
    int ar = lane & 15, ak = (lane >> 4) * 16;             // A: row, k-byte
    int nr = (lane & 7) + ((lane >> 4) << 3);              // W: n-row
    int nk = ((lane >> 3) & 1) * 16;                       // W: k-byte

    auto load_stage = [&](int st, int c) {
        const __nv_bfloat16 *Ah, *Al; int Ks, kb;
        if (c * 32 < K1) { Ah = A1h; Al = A1l; Ks = K1; kb = c * 32; }
        else             { Ah = A2h; Al = A2l; Ks = K2; kb = c * 32 - K1; }
        uint32_t base = sb + st * 32768;
        #pragma unroll
        for (int q = 0; q < 2; q++) {
            int id = tid + q * 256;
            int row = id >> 2, cc = id & 3;
            int gr = bm + row;
            int sz = (gr < M) ? 16 : 0;
            int grc = (gr < M) ? gr : (M - 1);
            uint32_t so = base + sw64((uint32_t)(row * 64 + cc * 16));
            cpa16(so,         Ah  + (size_t)grc * Ks + kb + cc * 8, sz);
            cpa16(so + 8192,  Al  + (size_t)grc * Ks + kb + cc * 8, sz);
            cpa16(so + 16384, Wph + (size_t)(bn + row) * KT + c * 32 + cc * 8, 16);
            cpa16(so + 24576, Wpl + (size_t)(bn + row) * KT + c * 32 + cc * 8, 16);
        }
        asm volatile("cp.async.commit_group;" ::: "memory");
    };

    auto compute_stage = [&](int st) {
        uint32_t base = sb + st * 32768;
        #pragma unroll
        for (int kk = 0; kk < 2; kk++) {
            uint32_t A_[4][4], W1[4][2], W2[4][2];
            uint32_t aoff[4], woff[2];
            #pragma unroll
            for (int mt = 0; mt < 4; mt++) {
                aoff[mt] = sw64((uint32_t)((wm * 64 + mt * 16 + ar) * 64 + ak + kk * 32));
                ldsm4(A_[mt][0], A_[mt][1], A_[mt][2], A_[mt][3], base + aoff[mt]);
            }
            #pragma unroll
            for (int h2 = 0; h2 < 2; h2++) {
                woff[h2] = sw64((uint32_t)((wn * 32 + h2 * 16 + nr) * 64 + nk + kk * 32));
                ldsm4(W1[h2 * 2][0], W1[h2 * 2][1], W1[h2 * 2 + 1][0], W1[h2 * 2 + 1][1],
                      base + 16384 + woff[h2]);
            }
            // hi(A) x hi(W)
            #pragma unroll
            for (int mt = 0; mt < 4; mt++)
                #pragma unroll
                for (int nt = 0; nt < 4; nt++)
                    mma16816(acc[mt][nt], A_[mt], W1[nt][0], W1[nt][1]);
            // hi(A) x lo(W)
            #pragma unroll
            for (int h2 = 0; h2 < 2; h2++)
                ldsm4(W2[h2 * 2][0], W2[h2 * 2][1], W2[h2 * 2 + 1][0], W2[h2 * 2 + 1][1],
                      base + 24576 + woff[h2]);
            #pragma unroll
            for (int mt = 0; mt < 4; mt++)
                #pragma unroll
                for (int nt = 0; nt < 4; nt++)
                    mma16816(acc[mt][nt], A_[mt], W2[nt][0], W2[nt][1]);
            // lo(A) x hi(W) — reuse A_ registers
            #pragma unroll
            for (int mt = 0; mt < 4; mt++)
                ldsm4(A_[mt][0], A_[mt][1], A_[mt][2], A_[mt][3], base + 8192 + aoff[mt]);
            #pragma unroll
            for (int mt = 0; mt < 4; mt++)
                #pragma unroll
                for (int nt = 0; nt < 4; nt++)
                    mma16816(acc[mt][nt], A_[mt], W1[nt][0], W1[nt][1]);
        }
    };

    load_stage(0, 0);
    for (int c = 0; c < NC; c++) {
        if (c + 1 < NC) {
            load_stage((c + 1) & 1, c + 1);
            asm volatile("cp.async.wait_group 1;" ::: "memory");
        } else {
            asm volatile("cp.async.wait_group 0;" ::: "memory");
        }
        __syncthreads();
        compute_stage(c & 1);
        __syncthreads();
    }

    // epilogue: bias + relu, split to hi/lo planes
    int g = lane >> 2, t = lane & 3;
    #pragma unroll
    for (int nt = 0; nt < 4; nt++) {
        int col = bn + wn * 32 + nt * 8 + 2 * t;
        float2 bv = *(const float2*)(bias + col);
        #pragma unroll
        for (int mt = 0; mt < 4; mt++) {
            int r0 = bm + wm * 64 + mt * 16 + g;
            int r1 = r0 + 8;
            if (r0 < M) {
                float f0 = fmaxf(acc[mt][nt][0] + bv.x, 0.f);
                float f1 = fmaxf(acc[mt][nt][1] + bv.y, 0.f);
                __nv_bfloat16 h0, l0, h1, l1;
                split2(f0, h0, l0); split2(f1, h1, l1);
                __nv_bfloat162 ph = __halves2bfloat162(h0, h1);
                __nv_bfloat162 pl = __halves2bfloat162(l0, l1);
                *(uint32_t*)(Oh + (size_t)r0 * NT + col) = *(uint32_t*)&ph;
                *(uint32_t*)(Ol + (size_t)r0 * NT + col) = *(uint32_t*)&pl;
            }
            if (r1 < M) {
                float f0 = fmaxf(acc[mt][nt][2] + bv.x, 0.f);
                float f1 = fmaxf(acc[mt][nt][3] + bv.y, 0.f);
                __nv_bfloat16 h0, l0, h1, l1;
                split2(f0, h0, l0); split2(f1, h1, l1);
                __nv_bfloat162 ph = __halves2bfloat162(h0, h1);
                __nv_bfloat162 pl = __halves2bfloat162(l0, l1);
                *(uint32_t*)(Oh + (size_t)r1 * NT + col) = *(uint32_t*)&ph;
                *(uint32_t*)(Ol + (size_t)r1 * NT + col) = *(uint32_t*)&pl;
            }
        }
    }
}

// ---------------- final FC: out = (hi+lo) @ Wfc + bfc  (256 -> 9), warp per node ----------------
__global__ void k_fc(const __nv_bfloat16* __restrict__ hh, const __nv_bfloat16* __restrict__ hl,
                     const float* __restrict__ W, const float* __restrict__ b,
                     float* __restrict__ out, int n) {
    __shared__ float sW[256 * 9];
    __shared__ float sb[9];
    for (int i = threadIdx.x; i < 256 * 9; i += blockDim.x) sW[i] = W[i];
    if (threadIdx.x < 9) sb[threadIdx.x] = b[threadIdx.x];
    __syncthreads();
    int warp = threadIdx.x >> 5, lane = threadIdx.x & 31;
    int node = blockIdx.x * 8 + warp;
    if (node >= n) return;
    float hv[8];
    #pragma unroll
    for (int r = 0; r < 8; r++) {
        size_t o = (size_t)node * 256 + r * 32 + lane;
        hv[r] = __bfloat162float(hh[o]) + __bfloat162float(hl[o]);
    }
    #pragma unroll
    for (int j = 0; j < 9; j++) {
        float s = 0.f;
        #pragma unroll
        for (int r = 0; r < 8; r++) s += hv[r] * sW[(r * 32 + lane) * 9 + j];
        #pragma unroll
        for (int o = 16; o > 0; o >>= 1) s += __shfl_xor_sync(0xffffffffu, s, o);
        if (lane == 0) out[node * 9 + j] = s + sb[j];
    }
}

// ---------------- launch ----------------
extern "C" void kernel_launch(void* const* d_in, const int* in_sizes, int n_in,
                              void* d_out, int out_size) {
    (void)n_in; (void)out_size;
    const float* x   = (const float*)d_in[0];
    const int*   ei  = (const int*)d_in[1];
    const float* Wl1 = (const float*)d_in[2];
    const float* bl1 = (const float*)d_in[3];
    const float* Wr1 = (const float*)d_in[4];
    const float* Wl2 = (const float*)d_in[5];
    const float* bl2 = (const float*)d_in[6];
    const float* Wr2 = (const float*)d_in[7];
    const float* Wl3 = (const float*)d_in[8];
    const float* bl3 = (const float*)d_in[9];
    const float* Wr3 = (const float*)d_in[10];
    const float* Wfc = (const float*)d_in[11];
    const float* bfc = (const float*)d_in[12];
    float* out = (float*)d_out;

    int M = in_sizes[0] / 64;
    int E = in_sizes[1] / 2;
    const int* src = ei;
    const int* dst = ei + E;

    __nv_bfloat16 *xh, *xl, *mh, *ml, *h1h, *h1l, *h2h, *h2l, *h3h, *h3l, *wth, *wtl;
    cudaGetSymbolAddress((void**)&xh,  g_xh);
    cudaGetSymbolAddress((void**)&xl,  g_xl);
    cudaGetSymbolAddress((void**)&mh,  g_mh);
    cudaGetSymbolAddress((void**)&ml,  g_ml);
    cudaGetSymbolAddress((void**)&h1h, g_h1h);
    cudaGetSymbolAddress((void**)&h1l, g_h1l);
    cudaGetSymbolAddress((void**)&h2h, g_h2h);
    cudaGetSymbolAddress((void**)&h2l, g_h2l);
    cudaGetSymbolAddress((void**)&h3h, g_h3h);
    cudaGetSymbolAddress((void**)&h3l, g_h3l);
    cudaGetSymbolAddress((void**)&wth, g_wth);
    cudaGetSymbolAddress((void**)&wtl, g_wtl);

    cudaFuncSetAttribute(k_gemm_cp<64, 64, 128>,
                         cudaFuncAttributeMaxDynamicSharedMemorySize, SM_TOT);
    cudaFuncSetAttribute(k_gemm_cp<128, 128, 128>,
                         cudaFuncAttributeMaxDynamicSharedMemorySize, SM_TOT);
    cudaFuncSetAttribute(k_gemm_cp<128, 128, 256>,
                         cudaFuncAttributeMaxDynamicSharedMemorySize, SM_TOT);

    int nbN = (M + 255) / 256;
    int nbE = (E + 255) / 256;
    int nbW = (M * 32 + 255) / 256;   // warp per node
    int gM  = (M + 127) / 128;        // 782

    // CSR build
    k_zero_deg<<<nbN, 256>>>(M);
    k_count<<<nbE, 256>>>(dst, E);
    k_scan1<<<nbN, 256>>>(M);
    k_scan2<<<1, 512>>>(nbN);
    k_scan3<<<nbN, 256>>>(M);
    k_fill<<<nbE, 256>>>(src, dst, E);

    // input split (x -> planes)
    k_split_x<<<(M * 16 + 255) / 256, 256>>>(x, M * 16);

    // ---- layer 1: 64 -> 128 ----
    k_prep_w<<<(128 * 128 + 255) / 256, 256>>>(Wl1, Wr1, 64, 128, 128);
    k_agg1<<<nbW, 256>>>(x, M);
    k_gemm_cp<64, 64, 128><<<dim3(1, gM), 256, SM_TOT>>>(
        mh, ml, xh, xl, wth, wtl, bl1, h1h, h1l, M);

    // ---- layer 2: 128 -> 128 ----
    k_prep_w<<<(128 * 256 + 255) / 256, 256>>>(Wl2, Wr2, 128, 256, 128);
    k_agg2<<<nbW, 256>>>(h1h, h1l, M);
    k_gemm_cp<128, 128, 128><<<dim3(1, gM), 256, SM_TOT>>>(
        mh, ml, h1h, h1l, wth, wtl, bl2, h2h, h2l, M);

    // ---- layer 3: 128 -> 256 ----
    k_prep_w<<<(256 * 256 + 255) / 256, 256>>>(Wl3, Wr3, 128, 256, 256);
    k_agg2<<<nbW, 256>>>(h2h, h2l, M);
    k_gemm_cp<128, 128, 256><<<dim3(2, gM), 256, SM_TOT>>>(
        mh, ml, h2h, h2l, wth, wtl, bl3, h3h, h3l, M);

    // ---- FC head: 256 -> 9 ----
    k_fc<<<(M + 7) / 8, 256>>>(h3h, h3l, Wfc, bfc, out, M);
}

// round 6
// speedup vs baseline: 1.0304x; 1.0304x over previous
#include <cuda_runtime.h>
#include <cuda_bf16.h>
#include <cuda_fp16.h>
#include <cstdint>

#define NNODES 100000
#define NEDGES 1600000

// ---------------- scratch (static __device__ — allocation-free) ----------------
__device__ int g_deg[NNODES], g_rowptr[NNODES], g_cursor[NNODES], g_col[NEDGES];
__device__ int g_bsum[512], g_boff[512];
__device__ float g_m [NNODES * 128];
__device__ float g_h1[NNODES * 128];
__device__ float g_h2[NNODES * 128];
__device__ float g_h3[NNODES * 256];
__device__ float g_wt[256 * 256];
// fp16 shadow copies for the gather (agg) read path only
__device__ __half g_xf [NNODES * 64];
__device__ __half g_hf1[NNODES * 128];
__device__ __half g_hf2[NNODES * 128];

// ---------------- helpers ----------------
__device__ __forceinline__ uint32_t sw128(uint32_t b) { return b ^ ((b >> 3) & 0x70); }
__device__ __forceinline__ uint32_t cvta_smem(const void* p) {
    uint32_t a;
    asm("{ .reg .u64 t; cvta.to.shared.u64 t, %1; cvt.u32.u64 %0, t; }" : "=r"(a) : "l"(p));
    return a;
}
__device__ __forceinline__ void ldsm4(uint32_t& r0, uint32_t& r1, uint32_t& r2, uint32_t& r3,
                                      uint32_t addr) {
    asm volatile("ldmatrix.sync.aligned.m8n8.x4.shared.b16 {%0,%1,%2,%3}, [%4];"
                 : "=r"(r0), "=r"(r1), "=r"(r2), "=r"(r3) : "r"(addr));
}
__device__ __forceinline__ void mma16816(float* c, const uint32_t* a, uint32_t b0, uint32_t b1) {
    asm volatile(
        "mma.sync.aligned.m16n8k16.row.col.f32.bf16.bf16.f32 "
        "{%0,%1,%2,%3}, {%4,%5,%6,%7}, {%8,%9}, {%0,%1,%2,%3};"
        : "+f"(c[0]), "+f"(c[1]), "+f"(c[2]), "+f"(c[3])
        : "r"(a[0]), "r"(a[1]), "r"(a[2]), "r"(a[3]), "r"(b0), "r"(b1));
}
// split 4 fp32 -> 4 bf16 hi (8B) + 4 bf16 lo (8B)
__device__ __forceinline__ void split4(float4 v, uint2& H, uint2& L) {
    __nv_bfloat16 h0 = __float2bfloat16(v.x), h1 = __float2bfloat16(v.y);
    __nv_bfloat16 h2 = __float2bfloat16(v.z), h3 = __float2bfloat16(v.w);
    __nv_bfloat16 l0 = __float2bfloat16(v.x - __bfloat162float(h0));
    __nv_bfloat16 l1 = __float2bfloat16(v.y - __bfloat162float(h1));
    __nv_bfloat16 l2 = __float2bfloat16(v.z - __bfloat162float(h2));
    __nv_bfloat16 l3 = __float2bfloat16(v.w - __bfloat162float(h3));
    __nv_bfloat162 ph0 = __halves2bfloat162(h0, h1), ph1 = __halves2bfloat162(h2, h3);
    __nv_bfloat162 pl0 = __halves2bfloat162(l0, l1), pl1 = __halves2bfloat162(l2, l3);
    H = make_uint2(*(uint32_t*)&ph0, *(uint32_t*)&ph1);
    L = make_uint2(*(uint32_t*)&pl0, *(uint32_t*)&pl1);
}

// ---------------- CSR build ----------------
__global__ void k_zero_deg(int n) {
    int i = blockIdx.x * blockDim.x + threadIdx.x;
    if (i < n) g_deg[i] = 0;
}
__global__ void k_count(const int* __restrict__ dst, int E) {
    int e = blockIdx.x * blockDim.x + threadIdx.x;
    if (e < E) atomicAdd(&g_deg[dst[e]], 1);
}
__global__ void k_scan1(int n) {
    int tid = threadIdx.x, lane = tid & 31, warp = tid >> 5;
    int i = blockIdx.x * 256 + tid;
    int v = (i < n) ? g_deg[i] : 0;
    int x = v;
    #pragma unroll
    for (int o = 1; o < 32; o <<= 1) {
        int t = __shfl_up_sync(0xffffffffu, x, o);
        if (lane >= o) x += t;
    }
    __shared__ int wq[8];
    if (lane == 31) wq[warp] = x;
    __syncthreads();
    if (warp == 0) {
        int y = (lane < 8) ? wq[lane] : 0;
        int z = y;
        #pragma unroll
        for (int o = 1; o < 8; o <<= 1) {
            int t = __shfl_up_sync(0xffffffffu, z, o);
            if (lane >= o) z += t;
        }
        if (lane < 8) wq[lane] = z - y;
        if (lane == 7) g_bsum[blockIdx.x] = z;
    }
    __syncthreads();
    if (i < n) g_rowptr[i] = wq[warp] + x - v;
}
__global__ void k_scan2(int nb) {
    int tid = threadIdx.x, lane = tid & 31, warp = tid >> 5;
    int v = (tid < nb) ? g_bsum[tid] : 0;
    int x = v;
    #pragma unroll
    for (int o = 1; o < 32; o <<= 1) {
        int t = __shfl_up_sync(0xffffffffu, x, o);
        if (lane >= o) x += t;
    }
    __shared__ int wq[16];
    if (lane == 31) wq[warp] = x;
    __syncthreads();
    if (warp == 0) {
        int y = (lane < 16) ? wq[lane] : 0;
        int z = y;
        #pragma unroll
        for (int o = 1; o < 16; o <<= 1) {
            int t = __shfl_up_sync(0xffffffffu, z, o);
            if (lane >= o) z += t;
        }
        if (lane < 16) wq[lane] = z - y;
    }
    __syncthreads();
    if (tid < nb) g_boff[tid] = wq[warp] + x - v;
}
__global__ void k_scan3(int n) {
    int i = blockIdx.x * blockDim.x + threadIdx.x;
    if (i < n) {
        int r = g_rowptr[i] + g_boff[i >> 8];
        g_rowptr[i] = r;
        g_cursor[i] = r;
    }
}
__global__ void k_fill(const int* __restrict__ src, const int* __restrict__ dst, int E) {
    int e = blockIdx.x * blockDim.x + threadIdx.x;
    if (e < E) {
        int p = atomicAdd(&g_cursor[dst[e]], 1);
        g_col[p] = src[e];
    }
}

// ---------------- x -> fp16 shadow ----------------
__global__ void k_cvt_half(const float* __restrict__ x, __half* __restrict__ xf, int n2) {
    int i = blockIdx.x * blockDim.x + threadIdx.x;
    if (i < n2) {
        float2 v = *(const float2*)(x + i * 2);
        *(__half2*)(xf + i * 2) = __floats2half2_rn(v.x, v.y);
    }
}

// ---------------- weight prep: g_wt[n][k] = (k<K1 ? Wl[k][n] : Wr[k-K1][n]) ----------------
__global__ void k_prep_w(const float* __restrict__ Wl, const float* __restrict__ Wr,
                         int K1, int KT, int N) {
    int i = blockIdx.x * blockDim.x + threadIdx.x;
    if (i >= N * KT) return;
    int n = i / KT, k = i % KT;
    g_wt[n * KT + k] = (k < K1) ? Wl[k * N + n] : Wr[(k - K1) * N + n];
}

// ---------------- mean aggregation (fp16 gather, fp32 accumulate, warp per node) ----------------
// D=64: lane owns 2 elems (half2 load)
__global__ void k_agg1h(const __half* __restrict__ xf, float* __restrict__ m, int n) {
    int gt = blockIdx.x * blockDim.x + threadIdx.x;
    int node = gt >> 5, lane = gt & 31;
    if (node >= n) return;
    float a0 = 0.f, a1 = 0.f;
    int s = g_rowptr[node], d = g_deg[node];
    int e = s, end = s + d;
    for (; e + 1 < end; e += 2) {
        float2 p0 = __half22float2(*(const __half2*)(xf + (size_t)g_col[e]     * 64 + 2 * lane));
        float2 p1 = __half22float2(*(const __half2*)(xf + (size_t)g_col[e + 1] * 64 + 2 * lane));
        a0 += p0.x + p1.x; a1 += p0.y + p1.y;
    }
    if (e < end) {
        float2 p0 = __half22float2(*(const __half2*)(xf + (size_t)g_col[e] * 64 + 2 * lane));
        a0 += p0.x; a1 += p0.y;
    }
    float inv = 1.0f / (float)(d > 0 ? d : 1);
    *(float2*)(m + (size_t)node * 64 + 2 * lane) = make_float2(a0 * inv, a1 * inv);
}
// D=128: lane owns 4 elems (uint2 = 4 halves)
__global__ void k_agg2h(const __half* __restrict__ hf, float* __restrict__ m, int n) {
    int gt = blockIdx.x * blockDim.x + threadIdx.x;
    int node = gt >> 5, lane = gt & 31;
    if (node >= n) return;
    float a0 = 0.f, a1 = 0.f, a2 = 0.f, a3 = 0.f;
    int s = g_rowptr[node], d = g_deg[node];
    int e = s, end = s + d;
    for (; e + 1 < end; e += 2) {
        uint2 u0 = *(const uint2*)(hf + (size_t)g_col[e]     * 128 + 4 * lane);
        uint2 u1 = *(const uint2*)(hf + (size_t)g_col[e + 1] * 128 + 4 * lane);
        float2 f0 = __half22float2(*(__half2*)&u0.x), f1 = __half22float2(*(__half2*)&u0.y);
        float2 f2 = __half22float2(*(__half2*)&u1.x), f3 = __half22float2(*(__half2*)&u1.y);
        a0 += f0.x + f2.x; a1 += f0.y + f2.y;
        a2 += f1.x + f3.x; a3 += f1.y + f3.y;
    }
    if (e < end) {
        uint2 u0 = *(const uint2*)(hf + (size_t)g_col[e] * 128 + 4 * lane);
        float2 f0 = __half22float2(*(__half2*)&u0.x), f1 = __half22float2(*(__half2*)&u0.y);
        a0 += f0.x; a1 += f0.y; a2 += f1.x; a3 += f1.y;
    }
    float inv = 1.0f / (float)(d > 0 ? d : 1);
    *(float4*)(m + (size_t)node * 128 + 4 * lane) =
        make_float4(a0 * inv, a1 * inv, a2 * inv, a3 * inv);
}

// ---------------- HMMA split-bf16 GEMM: out = relu([A1|A2] @ Wt^T + bias) ----------------
// A1:[M,K1] A2:[M,K2] fp32; Wt:[NT, KT] fp32 (g_wt); out:[M,NT] fp32 (+ optional fp16 shadow).
// CTA 128x128, 8 warps (2m x 4n), warp tile 64x32, K-chunk 64. smem 64KB, 2 CTAs/SM.
#define SM_AH 0
#define SM_AL 16384
#define SM_WH 32768
#define SM_WL 49152
#define SM_TOT 65536

template <int K1, int K2, int NT>
__global__ void __launch_bounds__(256, 2) k_gemm_mma(
    const float* __restrict__ A1, const float* __restrict__ A2,
    const float* __restrict__ Wt, const float* __restrict__ bias,
    float* __restrict__ out, __half* __restrict__ Of, int M)
{
    extern __shared__ char smem[];
    constexpr int KT = K1 + K2;
    constexpr int NC = KT / 64;
    uint32_t sb = cvta_smem(smem);
    int tid = threadIdx.x, lane = tid & 31, wid = tid >> 5;
    int wm = wid & 1, wn = wid >> 1;           // 2 x 4 warp grid
    int bm = blockIdx.y * 128, bn = blockIdx.x * 128;

    float acc[4][4][4];
    #pragma unroll
    for (int mt = 0; mt < 4; mt++)
        #pragma unroll
        for (int nt = 0; nt < 4; nt++)
            #pragma unroll
            for (int j = 0; j < 4; j++) acc[mt][nt][j] = 0.f;

    // per-lane ldmatrix address components (x4, non-trans)
    int ar = lane & 15, ak = (lane >> 4) * 16;             // A: row, k-byte
    int nr = (lane & 7) + ((lane >> 4) << 3);              // W: n-row
    int nk = ((lane >> 3) & 1) * 16;                       // W: k-byte

    for (int c = 0; c < NC; c++) {
        const float* A; int Ks, kb;
        if (c * 64 < K1) { A = A1; Ks = K1; kb = c * 64; }
        else             { A = A2; Ks = K2; kb = c * 64 - K1; }

        // fill A tiles (hi/lo), 128 rows x 64 k
        #pragma unroll
        for (int p = 0; p < 8; p++) {
            int id = tid + p * 256;
            int row = id >> 4, kc = id & 15;
            int gr = bm + row;
            float4 v = make_float4(0.f, 0.f, 0.f, 0.f);
            if (gr < M) v = *(const float4*)(A + (size_t)gr * Ks + kb + kc * 4);
            uint2 H, L; split4(v, H, L);
            uint32_t so = sw128((uint32_t)(row * 128 + kc * 8));
            *(uint2*)(smem + SM_AH + so) = H;
            *(uint2*)(smem + SM_AL + so) = L;
        }
        // fill W tiles (hi/lo), 128 n-rows x 64 k
        #pragma unroll
        for (int p = 0; p < 8; p++) {
            int id = tid + p * 256;
            int row = id >> 4, kc = id & 15;
            float4 v = *(const float4*)(Wt + (size_t)(bn + row) * KT + c * 64 + kc * 4);
            uint2 H, L; split4(v, H, L);
            uint32_t so = sw128((uint32_t)(row * 128 + kc * 8));
            *(uint2*)(smem + SM_WH + so) = H;
            *(uint2*)(smem + SM_WL + so) = L;
        }
        __syncthreads();

        #pragma unroll
        for (int kk = 0; kk < 4; kk++) {
            uint32_t Ah[4][4], Al[4][4], Wh[4][2], Wl[4][2];
            #pragma unroll
            for (int mt = 0; mt < 4; mt++) {
                uint32_t off = sw128((uint32_t)((wm * 64 + mt * 16 + ar) * 128 + ak + kk * 32));
                ldsm4(Ah[mt][0], Ah[mt][1], Ah[mt][2], Ah[mt][3], sb + SM_AH + off);
            }
            #pragma unroll
            for (int h2 = 0; h2 < 2; h2++) {
                uint32_t off = sw128((uint32_t)((wn * 32 + h2 * 16 + nr) * 128 + nk + kk * 32));
                ldsm4(Wh[h2 * 2][0], Wh[h2 * 2][1], Wh[h2 * 2 + 1][0], Wh[h2 * 2 + 1][1],
                      sb + SM_WH + off);
            }
            #pragma unroll
            for (int mt = 0; mt < 4; mt++)
                #pragma unroll
                for (int nt = 0; nt < 4; nt++)
                    mma16816(acc[mt][nt], Ah[mt], Wh[nt][0], Wh[nt][1]);
            // lo(A) x hi(W)
            #pragma unroll
            for (int mt = 0; mt < 4; mt++) {
                uint32_t off = sw128((uint32_t)((wm * 64 + mt * 16 + ar) * 128 + ak + kk * 32));
                ldsm4(Al[mt][0], Al[mt][1], Al[mt][2], Al[mt][3], sb + SM_AL + off);
            }
            #pragma unroll
            for (int mt = 0; mt < 4; mt++)
                #pragma unroll
                for (int nt = 0; nt < 4; nt++)
                    mma16816(acc[mt][nt], Al[mt], Wh[nt][0], Wh[nt][1]);
            // hi(A) x lo(W)
            #pragma unroll
            for (int h2 = 0; h2 < 2; h2++) {
                uint32_t off = sw128((uint32_t)((wn * 32 + h2 * 16 + nr) * 128 + nk + kk * 32));
                ldsm4(Wl[h2 * 2][0], Wl[h2 * 2][1], Wl[h2 * 2 + 1][0], Wl[h2 * 2 + 1][1],
                      sb + SM_WL + off);
            }
            #pragma unroll
            for (int mt = 0; mt < 4; mt++)
                #pragma unroll
                for (int nt = 0; nt < 4; nt++)
                    mma16816(acc[mt][nt], Ah[mt], Wl[nt][0], Wl[nt][1]);
        }
        __syncthreads();
    }

    // epilogue: bias + relu, fp32 store + optional fp16 shadow
    int g = lane >> 2, t = lane & 3;
    #pragma unroll
    for (int nt = 0; nt < 4; nt++) {
        int col = bn + wn * 32 + nt * 8 + 2 * t;
        float2 bv = *(const float2*)(bias + col);
        #pragma unroll
        for (int mt = 0; mt < 4; mt++) {
            int r0 = bm + wm * 64 + mt * 16 + g;
            int r1 = r0 + 8;
            if (r0 < M) {
                float2 w = make_float2(fmaxf(acc[mt][nt][0] + bv.x, 0.f),
                                       fmaxf(acc[mt][nt][1] + bv.y, 0.f));
                *(float2*)(out + (size_t)r0 * NT + col) = w;
                if (Of) *(__half2*)(Of + (size_t)r0 * NT + col) = __floats2half2_rn(w.x, w.y);
            }
            if (r1 < M) {
                float2 w = make_float2(fmaxf(acc[mt][nt][2] + bv.x, 0.f),
                                       fmaxf(acc[mt][nt][3] + bv.y, 0.f));
                *(float2*)(out + (size_t)r1 * NT + col) = w;
                if (Of) *(__half2*)(Of + (size_t)r1 * NT + col) = __floats2half2_rn(w.x, w.y);
            }
        }
    }
}

// ---------------- final FC: out = h3 @ Wfc + bfc  (256 -> 9), warp per node ----------------
__global__ void k_fc(const float* __restrict__ h, const float* __restrict__ W,
                     const float* __restrict__ b, float* __restrict__ out, int n) {
    __shared__ float sW[256 * 9];
    __shared__ float sb[9];
    for (int i = threadIdx.x; i < 256 * 9; i += blockDim.x) sW[i] = W[i];
    if (threadIdx.x < 9) sb[threadIdx.x] = b[threadIdx.x];
    __syncthreads();
    int warp = threadIdx.x >> 5, lane = threadIdx.x & 31;
    int node = blockIdx.x * 8 + warp;
    if (node >= n) return;
    float hv[8];
    #pragma unroll
    for (int r = 0; r < 8; r++) hv[r] = h[(size_t)node * 256 + r * 32 + lane];
    #pragma unroll
    for (int j = 0; j < 9; j++) {
        float s = 0.f;
        #pragma unroll
        for (int r = 0; r < 8; r++) s += hv[r] * sW[(r * 32 + lane) * 9 + j];
        #pragma unroll
        for (int o = 16; o > 0; o >>= 1) s += __shfl_xor_sync(0xffffffffu, s, o);
        if (lane == 0) out[node * 9 + j] = s + sb[j];
    }
}

// ---------------- launch ----------------
extern "C" void kernel_launch(void* const* d_in, const int* in_sizes, int n_in,
                              void* d_out, int out_size) {
    (void)n_in; (void)out_size;
    const float* x   = (const float*)d_in[0];
    const int*   ei  = (const int*)d_in[1];
    const float* Wl1 = (const float*)d_in[2];
    const float* bl1 = (const float*)d_in[3];
    const float* Wr1 = (const float*)d_in[4];
    const float* Wl2 = (const float*)d_in[5];
    const float* bl2 = (const float*)d_in[6];
    const float* Wr2 = (const float*)d_in[7];
    const float* Wl3 = (const float*)d_in[8];
    const float* bl3 = (const float*)d_in[9];
    const float* Wr3 = (const float*)d_in[10];
    const float* Wfc = (const float*)d_in[11];
    const float* bfc = (const float*)d_in[12];
    float* out = (float*)d_out;

    int M = in_sizes[0] / 64;
    int E = in_sizes[1] / 2;
    const int* src = ei;
    const int* dst = ei + E;

    float *pm, *ph1, *ph2, *ph3, *pwt;
    __half *pxf, *phf1, *phf2;
    cudaGetSymbolAddress((void**)&pm,  g_m);
    cudaGetSymbolAddress((void**)&ph1, g_h1);
    cudaGetSymbolAddress((void**)&ph2, g_h2);
    cudaGetSymbolAddress((void**)&ph3, g_h3);
    cudaGetSymbolAddress((void**)&pwt, g_wt);
    cudaGetSymbolAddress((void**)&pxf, g_xf);
    cudaGetSymbolAddress((void**)&phf1, g_hf1);
    cudaGetSymbolAddress((void**)&phf2, g_hf2);

    cudaFuncSetAttribute(k_gemm_mma<64, 64, 128>,
                         cudaFuncAttributeMaxDynamicSharedMemorySize, SM_TOT);
    cudaFuncSetAttribute(k_gemm_mma<128, 128, 128>,
                         cudaFuncAttributeMaxDynamicSharedMemorySize, SM_TOT);
    cudaFuncSetAttribute(k_gemm_mma<128, 128, 256>,
                         cudaFuncAttributeMaxDynamicSharedMemorySize, SM_TOT);

    int nbN = (M + 255) / 256;
    int nbE = (E + 255) / 256;
    int nbW = (M * 32 + 255) / 256;   // warp per node
    int gM  = (M + 127) / 128;        // 782

    // CSR build
    k_zero_deg<<<nbN, 256>>>(M);
    k_count<<<nbE, 256>>>(dst, E);
    k_scan1<<<nbN, 256>>>(M);
    k_scan2<<<1, 512>>>(nbN);
    k_scan3<<<nbN, 256>>>(M);
    k_fill<<<nbE, 256>>>(src, dst, E);

    // x -> fp16 shadow (for gather path)
    k_cvt_half<<<(M * 32 + 255) / 256, 256>>>(x, pxf, M * 32);

    // ---- layer 1: 64 -> 128 ----
    k_prep_w<<<(128 * 128 + 255) / 256, 256>>>(Wl1, Wr1, 64, 128, 128);
    k_agg1h<<<nbW, 256>>>(pxf, pm, M);
    k_gemm_mma<64, 64, 128><<<dim3(1, gM), 256, SM_TOT>>>(pm, x, pwt, bl1, ph1, phf1, M);

    // ---- layer 2: 128 -> 128 ----
    k_prep_w<<<(128 * 256 + 255) / 256, 256>>>(Wl2, Wr2, 128, 256, 128);
    k_agg2h<<<nbW, 256>>>(phf1, pm, M);
    k_gemm_mma<128, 128, 128><<<dim3(1, gM), 256, SM_TOT>>>(pm, ph1, pwt, bl2, ph2, phf2, M);

    // ---- layer 3: 128 -> 256 ----
    k_prep_w<<<(256 * 256 + 255) / 256, 256>>>(Wl3, Wr3, 128, 256, 256);
    k_agg2h<<<nbW, 256>>>(phf2, pm, M);
    k_gemm_mma<128, 128, 256><<<dim3(2, gM), 256, SM_TOT>>>(pm, ph2, pwt, bl3, ph3,
                                                            (__half*)nullptr, M);

    // ---- FC head: 256 -> 9 ----
    k_fc<<<(M + 7) / 8, 256>>>(ph3, Wfc, bfc, out, M);
}